// round 2
// baseline (speedup 1.0000x reference)
#include <cuda_runtime.h>
#include <cstdint>

// RAPiD decode: raw (64,18,128,128) f32 -> pred (64, 3*128*128, 6) f32
// px = (sig(r0)+x)/W*img_w ; py = (sig(r1)+y)/H*img_h
// pw = exp(r2)*aw ; ph = exp(r3)*ah ; pa = sig(r4)*360-180 ; conf = sig(r5)

static constexpr int NB = 64;
static constexpr int NA = 3;
static constexpr int NH = 128;
static constexpr int NW = 128;
static constexpr int HW = NH * NW;          // 16384
static constexpr int CELLS = NB * NA * HW;  // 3,145,728
static constexpr int TPB = 256;
static constexpr int VEC = 4;
static constexpr int CPB = TPB * VEC;       // 1024 cells per block

__device__ __forceinline__ float htanh(float x) {
    float y;
    asm("tanh.approx.f32 %0, %1;" : "=f"(y) : "f"(x));
    return y;
}
// sigmoid(x) = 0.5*tanh(x/2) + 0.5  (1 MUFU + FMAs)
__device__ __forceinline__ float fsig(float x) {
    return fmaf(htanh(0.5f * x), 0.5f, 0.5f);
}

__global__ void __launch_bounds__(TPB) rapid_decode_kernel(
    const float* __restrict__ raw,
    const float* __restrict__ anchors,
    const int* __restrict__ p_img_h,
    const int* __restrict__ p_img_w,
    float* __restrict__ out)
{
    __shared__ float s[6][CPB];   // field-major staging

    const int tid = threadIdx.x;
    const int c0  = blockIdx.x * CPB + tid * VEC;  // first cell of this thread

    const int w0  = c0 & (NW - 1);          // multiple of 4, no row crossing
    const int h   = (c0 >> 7) & (NH - 1);
    const int ahw = c0 >> 14;               // b*3 + a (constant over 4 cells)
    const int a   = ahw % 3;
    const int b   = ahw / 3;

    const float sw = (float)__ldg(p_img_w) * (1.0f / (float)NW);
    const float sh = (float)__ldg(p_img_h) * (1.0f / (float)NH);
    const float aw = __ldg(anchors + 2 * a);
    const float ah = __ldg(anchors + 2 * a + 1);

    // input: raw[b, a*6 + f, h, w], channel stride HW; float4 over w
    const size_t in_base = ((size_t)(b * 18 + a * 6) << 14) + (size_t)(c0 & (HW - 1));
    const float4* p = reinterpret_cast<const float4*>(raw + in_base);
    const float4 r0 = __ldg(p);
    const float4 r1 = __ldg(p + 1 * (HW / 4));
    const float4 r2 = __ldg(p + 2 * (HW / 4));
    const float4 r3 = __ldg(p + 3 * (HW / 4));
    const float4 r4 = __ldg(p + 4 * (HW / 4));
    const float4 r5 = __ldg(p + 5 * (HW / 4));

    const float py1  = (fsig(r1.x) + (float)h) * sh;   // same h for all 4
    const float py2  = (fsig(r1.y) + (float)h) * sh;
    const float py3  = (fsig(r1.z) + (float)h) * sh;
    const float py4  = (fsig(r1.w) + (float)h) * sh;

    float4 vx, vy, vw, vh, va, vc;
    vx.x = (fsig(r0.x) + (float)(w0 + 0)) * sw;
    vx.y = (fsig(r0.y) + (float)(w0 + 1)) * sw;
    vx.z = (fsig(r0.z) + (float)(w0 + 2)) * sw;
    vx.w = (fsig(r0.w) + (float)(w0 + 3)) * sw;
    vy.x = py1; vy.y = py2; vy.z = py3; vy.w = py4;
    vw.x = __expf(r2.x) * aw;  vw.y = __expf(r2.y) * aw;
    vw.z = __expf(r2.z) * aw;  vw.w = __expf(r2.w) * aw;
    vh.x = __expf(r3.x) * ah;  vh.y = __expf(r3.y) * ah;
    vh.z = __expf(r3.z) * ah;  vh.w = __expf(r3.w) * ah;
    va.x = fsig(r4.x) * 360.0f - 180.0f;
    va.y = fsig(r4.y) * 360.0f - 180.0f;
    va.z = fsig(r4.z) * 360.0f - 180.0f;
    va.w = fsig(r4.w) * 360.0f - 180.0f;
    vc.x = fsig(r5.x); vc.y = fsig(r5.y); vc.z = fsig(r5.z); vc.w = fsig(r5.w);

    // conflict-free STS.128 per field
    reinterpret_cast<float4*>(s[0])[tid] = vx;
    reinterpret_cast<float4*>(s[1])[tid] = vy;
    reinterpret_cast<float4*>(s[2])[tid] = vw;
    reinterpret_cast<float4*>(s[3])[tid] = vh;
    reinterpret_cast<float4*>(s[4])[tid] = va;
    reinterpret_cast<float4*>(s[5])[tid] = vc;

    __syncthreads();

    // flush: block's contiguous 6144-float span, coalesced STG.128
    float4* ob = reinterpret_cast<float4*>(out + (size_t)blockIdx.x * (CPB * 6));
    const float* sf = &s[0][0];
    #pragma unroll
    for (int it = 0; it < 6; ++it) {
        const int q = tid + it * TPB;   // float4 index 0..1535
        const int o = q * 4;            // float index within block span
        float4 v;
        v.x = s[(o + 0) % 6][(o + 0) / 6];
        v.y = s[(o + 1) % 6][(o + 1) / 6];
        v.z = s[(o + 2) % 6][(o + 2) / 6];
        v.w = s[(o + 3) % 6][(o + 3) / 6];
        ob[q] = v;
    }
    (void)sf;
}

extern "C" void kernel_launch(void* const* d_in, const int* in_sizes, int n_in,
                              void* d_out, int out_size)
{
    const float* raw     = (const float*)d_in[0];
    const float* anchors = (const float*)d_in[1];
    const int*   img_h   = (const int*)d_in[2];
    const int*   img_w   = (const int*)d_in[3];
    float* out = (float*)d_out;

    const int blocks = CELLS / CPB;  // 3072
    rapid_decode_kernel<<<blocks, TPB>>>(raw, anchors, img_h, img_w, out);
}

// round 3
// speedup vs baseline: 1.1429x; 1.1429x over previous
#include <cuda_runtime.h>
#include <cstdint>

// RAPiD decode: raw (64,18,128,128) f32 -> pred (64, 3*128*128, 6) f32
// per cell: px=(sig(r0)+x)/W*img_w ; py=(sig(r1)+y)/H*img_h
//           pw=exp(r2)*aw ; ph=exp(r3)*ah ; pa=sig(r4)*360-180 ; conf=sig(r5)
// Direct-store version: 2 cells/thread -> 3 contiguous STG.128, no smem.

static constexpr int NB = 64;
static constexpr int NA = 3;
static constexpr int NH = 128;
static constexpr int NW = 128;
static constexpr int HW = NH * NW;          // 16384
static constexpr int CELLS = NB * NA * HW;  // 3,145,728
static constexpr int TPB = 256;
static constexpr int VEC = 2;
static constexpr int CPB = TPB * VEC;       // 512 cells per block

__device__ __forceinline__ float htanh(float x) {
    float y;
    asm("tanh.approx.f32 %0, %1;" : "=f"(y) : "f"(x));
    return y;
}
// sigmoid(x) = 0.5*tanh(x/2) + 0.5   (1 MUFU + 1 FMA)
__device__ __forceinline__ float fsig(float x) {
    return fmaf(htanh(0.5f * x), 0.5f, 0.5f);
}

__global__ void __launch_bounds__(TPB) rapid_decode_kernel(
    const float* __restrict__ raw,
    const float* __restrict__ anchors,
    const int* __restrict__ p_img_h,
    const int* __restrict__ p_img_w,
    float* __restrict__ out)
{
    const int tid = threadIdx.x;
    const int c0  = blockIdx.x * CPB + tid * VEC;  // first of 2 consecutive cells

    const int w0  = c0 & (NW - 1);          // even; pair stays in one row
    const int h   = (c0 >> 7) & (NH - 1);
    const int ahw = c0 >> 14;               // b*3 + a (constant over the pair)
    const int a   = ahw % 3;
    const int b   = ahw / 3;

    const float sw = (float)__ldg(p_img_w) * (1.0f / (float)NW);
    const float sh = (float)__ldg(p_img_h) * (1.0f / (float)NH);
    const float aw = __ldg(anchors + 2 * a);
    const float ah = __ldg(anchors + 2 * a + 1);

    // input: raw[b, a*6 + f, h, w], channel stride HW; float2 over w
    const size_t in_base = ((size_t)(b * 18 + a * 6) << 14) + (size_t)(c0 & (HW - 1));
    const float2* p = reinterpret_cast<const float2*>(raw + in_base);
    const float2 r0 = __ldg(p);
    const float2 r1 = __ldg(p + 1 * (HW / 2));
    const float2 r2 = __ldg(p + 2 * (HW / 2));
    const float2 r3 = __ldg(p + 3 * (HW / 2));
    const float2 r4 = __ldg(p + 4 * (HW / 2));
    const float2 r5 = __ldg(p + 5 * (HW / 2));

    const float fh = (float)h;

    float4 o0, o1, o2;
    // cell 0: px py pw ph | pa conf
    o0.x = (fsig(r0.x) + (float)(w0 + 0)) * sw;
    o0.y = (fsig(r1.x) + fh) * sh;
    o0.z = __expf(r2.x) * aw;
    o0.w = __expf(r3.x) * ah;
    o1.x = fsig(r4.x) * 360.0f - 180.0f;
    o1.y = fsig(r5.x);
    // cell 1
    o1.z = (fsig(r0.y) + (float)(w0 + 1)) * sw;
    o1.w = (fsig(r1.y) + fh) * sh;
    o2.x = __expf(r2.y) * aw;
    o2.y = __expf(r3.y) * ah;
    o2.z = fsig(r4.y) * 360.0f - 180.0f;
    o2.w = fsig(r5.y);

    // thread's 12 output floats are contiguous & 16B-aligned: 3x STG.128
    float4* ob = reinterpret_cast<float4*>(out + (size_t)c0 * 6);
    ob[0] = o0;
    ob[1] = o1;
    ob[2] = o2;
}

extern "C" void kernel_launch(void* const* d_in, const int* in_sizes, int n_in,
                              void* d_out, int out_size)
{
    const float* raw     = (const float*)d_in[0];
    const float* anchors = (const float*)d_in[1];
    const int*   img_h   = (const int*)d_in[2];
    const int*   img_w   = (const int*)d_in[3];
    float* out = (float*)d_out;

    const int blocks = CELLS / CPB;  // 6144
    rapid_decode_kernel<<<blocks, TPB>>>(raw, anchors, img_h, img_w, out);
}

// round 4
// speedup vs baseline: 1.2133x; 1.0616x over previous
#include <cuda_runtime.h>
#include <cstdint>

// RAPiD decode: raw (64,18,128,128) f32 -> pred (64, 3*128*128, 6) f32
// per cell: px=(sig(r0)+x)/W*img_w ; py=(sig(r1)+y)/H*img_h
//           pw=exp(r2)*aw ; ph=exp(r3)*ah ; pa=sig(r4)*360-180 ; conf=sig(r5)
// Staged version: float2 loads, cell-major smem (conflict-free STS.128),
// identity flush with coalesced STG.128.

static constexpr int NB = 64;
static constexpr int NA = 3;
static constexpr int NH = 128;
static constexpr int NW = 128;
static constexpr int HW = NH * NW;          // 16384
static constexpr int CELLS = NB * NA * HW;  // 3,145,728
static constexpr int TPB = 256;
static constexpr int VEC = 2;
static constexpr int CPB = TPB * VEC;       // 512 cells per block
static constexpr int F4_PER_BLOCK = CPB * 6 / 4;  // 768

__device__ __forceinline__ float htanh(float x) {
    float y;
    asm("tanh.approx.f32 %0, %1;" : "=f"(y) : "f"(x));
    return y;
}
// sigmoid(x) = 0.5*tanh(x/2) + 0.5   (1 MUFU + 1 FMA)
__device__ __forceinline__ float fsig(float x) {
    return fmaf(htanh(0.5f * x), 0.5f, 0.5f);
}

__global__ void __launch_bounds__(TPB) rapid_decode_kernel(
    const float* __restrict__ raw,
    const float* __restrict__ anchors,
    const int* __restrict__ p_img_h,
    const int* __restrict__ p_img_w,
    float* __restrict__ out)
{
    __shared__ float s[CPB * 6];   // cell-major staging, 12 KB

    const int tid = threadIdx.x;
    const int c0  = blockIdx.x * CPB + tid * VEC;  // first of 2 consecutive cells

    const int w0  = c0 & (NW - 1);          // even; pair stays within one row
    const int h   = (c0 >> 7) & (NH - 1);
    const int ahw = c0 >> 14;               // b*3 + a (constant over the pair)
    const int a   = ahw % 3;
    const int b   = ahw / 3;

    const float sw = (float)__ldg(p_img_w) * (1.0f / (float)NW);
    const float sh = (float)__ldg(p_img_h) * (1.0f / (float)NH);
    const float aw = __ldg(anchors + 2 * a);
    const float ah = __ldg(anchors + 2 * a + 1);

    // input: raw[b, a*6 + f, h, w], channel stride HW; float2 over w
    const size_t in_base = ((size_t)(b * 18 + a * 6) << 14) + (size_t)(c0 & (HW - 1));
    const float2* p = reinterpret_cast<const float2*>(raw + in_base);
    const float2 r0 = __ldg(p);
    const float2 r1 = __ldg(p + 1 * (HW / 2));
    const float2 r2 = __ldg(p + 2 * (HW / 2));
    const float2 r3 = __ldg(p + 3 * (HW / 2));
    const float2 r4 = __ldg(p + 4 * (HW / 2));
    const float2 r5 = __ldg(p + 5 * (HW / 2));

    const float fh = (float)h;

    float4 o0, o1, o2;
    // cell 0: px py pw ph | pa conf
    o0.x = (fsig(r0.x) + (float)(w0 + 0)) * sw;
    o0.y = (fsig(r1.x) + fh) * sh;
    o0.z = __expf(r2.x) * aw;
    o0.w = __expf(r3.x) * ah;
    o1.x = fsig(r4.x) * 360.0f - 180.0f;
    o1.y = fsig(r5.x);
    // cell 1
    o1.z = (fsig(r0.y) + (float)(w0 + 1)) * sw;
    o1.w = (fsig(r1.y) + fh) * sh;
    o2.x = __expf(r2.y) * aw;
    o2.y = __expf(r3.y) * ah;
    o2.z = fsig(r4.y) * 360.0f - 180.0f;
    o2.w = fsig(r5.y);

    // stage: 12 contiguous floats at s[12*tid] -> 3x STS.128, conflict-free
    float4* sp = reinterpret_cast<float4*>(s + tid * 12);
    sp[0] = o0;
    sp[1] = o1;
    sp[2] = o2;

    __syncthreads();

    // flush: identity copy of block's contiguous span, coalesced STG.128
    float* ob = out + (size_t)blockIdx.x * (CPB * 6);
    const float4* sv = reinterpret_cast<const float4*>(s);
    #pragma unroll
    for (int j = 0; j < F4_PER_BLOCK / TPB; ++j) {   // 3 iters
        const int q = tid + j * TPB;
        __stcs(reinterpret_cast<float4*>(ob) + q, sv[q]);
    }
}

extern "C" void kernel_launch(void* const* d_in, const int* in_sizes, int n_in,
                              void* d_out, int out_size)
{
    const float* raw     = (const float*)d_in[0];
    const float* anchors = (const float*)d_in[1];
    const int*   img_h   = (const int*)d_in[2];
    const int*   img_w   = (const int*)d_in[3];
    float* out = (float*)d_out;

    const int blocks = CELLS / CPB;  // 6144
    rapid_decode_kernel<<<blocks, TPB>>>(raw, anchors, img_h, img_w, out);
}